// round 7
// baseline (speedup 1.0000x reference)
#include <cuda_runtime.h>
#include <cuda_bf16.h>
#include <math.h>
#include <cstdint>

#define BB 512
#define ZI 16
#define TT 8
#define DD 128
#define MROWS (BB*ZI)   /* 8192 */
#define NCOLS (BB*TT)   /* 4096 */

#define NBLK (NCOLS/128)         /* 32 n-blocks */
#define MBLK (MROWS/128)         /* 64 m-blocks */
#define NCTA (NBLK*MBLK)         /* 2048 CTAs   */

// ---------------- scratch (static __device__, allocation-free) -------------
__device__ __nv_bfloat162 g_imgh [(size_t)MROWS * (DD/2)];   // 2 MB
__device__ __nv_bfloat162 g_texth[(size_t)NCOLS * (DD/2)];   // 1 MB
__device__ float g_diag[NCOLS];
__device__ float g_rowpart[NBLK * BB];             // per n-block row sums
__device__ float g_colpart[(size_t)MBLK * NCOLS];  // per m-block col sums
__device__ float g_logden[NCOLS];
__device__ float g_logrow[BB];
__device__ unsigned g_cnt;                         // zero-init, self-resetting

__device__ __forceinline__ uint32_t smem_u32(const void* p) {
    uint32_t a;
    asm("{ .reg .u64 t; cvta.to.shared.u64 t, %1; cvt.u32.u64 %0, t; }"
        : "=r"(a) : "l"(p));
    return a;
}

#define CPASYNC16(dst,src) \
    asm volatile("cp.async.ca.shared.global [%0], [%1], 16;" \
                 :: "r"(dst), "l"(src) : "memory")

#define LDSM4(r0,r1,r2,r3,addr) \
    asm volatile("ldmatrix.sync.aligned.m8n8.x4.shared.b16 {%0,%1,%2,%3}, [%4];" \
                 : "=r"(r0),"=r"(r1),"=r"(r2),"=r"(r3) : "r"(addr))

#define MMA16816(c,a0,a1,a2,a3,b0,b1) \
    asm volatile("mma.sync.aligned.m16n8k16.row.col.f32.bf16.bf16.f32 " \
                 "{%0,%1,%2,%3},{%4,%5,%6,%7},{%8,%9},{%0,%1,%2,%3};" \
                 : "+f"(c[0]),"+f"(c[1]),"+f"(c[2]),"+f"(c[3]) \
                 : "r"(a0),"r"(a1),"r"(a2),"r"(a3),"r"(b0),"r"(b1))

// ---------------------------------------------------------------------------
// 1) L2 normalize + convert to packed bf16. One warp per row of 128 floats.
// ---------------------------------------------------------------------------
__global__ void knorm(const float* __restrict__ img, const float* __restrict__ text) {
    int wid  = blockIdx.x * 8 + (threadIdx.x >> 5);
    int lane = threadIdx.x & 31;
    const float* src; __nv_bfloat162* dst;
    if (wid < MROWS) { src = img + (size_t)wid * DD;  dst = g_imgh + (size_t)wid * (DD/2); }
    else { int r = wid - MROWS; src = text + (size_t)r * DD; dst = g_texth + (size_t)r * (DD/2); }
    float4 v = ((const float4*)src)[lane];
    float s = v.x*v.x + v.y*v.y + v.z*v.z + v.w*v.w;
    #pragma unroll
    for (int o = 16; o; o >>= 1) s += __shfl_xor_sync(0xffffffffu, s, o);
    float inv = 1.0f / fmaxf(sqrtf(s), 1e-12f);
    dst[lane*2]   = __floats2bfloat162_rn(v.x*inv, v.y*inv);
    dst[lane*2+1] = __floats2bfloat162_rn(v.z*inv, v.w*inv);
}

// ---------------------------------------------------------------------------
// 2) HMMA GEMM 128x128x128, 2048 CTAs. Warp tile 32m x 64n (4 mq x 2 nh):
//    per kk-step 6 LDSM.x4 feed 16 MMAs (was 9 per 16) -> -33% smem traffic.
//    Fused max-over-i + exp + partial reductions + last-CTA finale.
// ---------------------------------------------------------------------------
#define RPITCH 272
#define TILE_B (128 * RPITCH)            /* 34816 */
#define SM_BYTES (2 * TILE_B)            /* 69632 dynamic */

__global__ void __launch_bounds__(256) kgemm(float* __restrict__ out) {
    extern __shared__ char sh[];
    char* shA = sh;
    char* shB = sh + TILE_B;
    __shared__ float scol[8 * 128];
    __shared__ float srow[8][2];
    __shared__ float sred[256];
    __shared__ unsigned slast;

    const int tid  = threadIdx.x;
    const int lane = tid & 31, w = tid >> 5;
    const int mq = w >> 1, nh = w & 1;            // warp = (m-quad, n-half)
    const int nb = blockIdx.x, mb = blockIdx.y;
    const int m0 = mb * 128, n0 = nb * 128;

    const uint32_t sAu = smem_u32(shA), sBu = smem_u32(shB);

    // ---- async tile loads: 128 rows x 256B, rows padded to 272B -----------
    const uint4* gA = (const uint4*)(g_imgh  + (size_t)m0 * (DD/2));
    const uint4* gB = (const uint4*)(g_texth + (size_t)n0 * (DD/2));
    #pragma unroll
    for (int it = tid; it < 2048; it += 256) {
        int row = it >> 4, q = it & 15;
        uint32_t so = row * RPITCH + q * 16;
        CPASYNC16(sAu + so, gA + it);
        CPASYNC16(sBu + so, gB + it);
    }
    asm volatile("cp.async.commit_group;" ::: "memory");
    asm volatile("cp.async.wait_group 0;" ::: "memory");
    __syncthreads();

    // A: two m16 tiles at rows mq*32 and mq*32+16
    const uint32_t aBase = sAu + (uint32_t)(mq * 32 + (lane & 15)) * RPITCH
                               + (uint32_t)(lane >> 4) * 16;
    // B: lanes 0-7 rows n..n+8 klo | 8-15 khi | 16-23 n+8..16 klo | 24-31 khi
    const uint32_t bBase = sBu + (uint32_t)(nh * 64 + (lane & 7) + ((lane >> 4) << 3)) * RPITCH
                               + (uint32_t)((lane >> 3) & 1) * 16;

    float c[2][8][4];
    #pragma unroll
    for (int m = 0; m < 2; m++)
        #pragma unroll
        for (int t = 0; t < 8; t++)
            #pragma unroll
            for (int j = 0; j < 4; j++) c[m][t][j] = 0.0f;

    #pragma unroll
    for (int kk = 0; kk < 8; kk++) {                 // K = 8 * 16
        uint32_t a0[4], a1[4];
        LDSM4(a0[0], a0[1], a0[2], a0[3], aBase + kk * 32);
        LDSM4(a1[0], a1[1], a1[2], a1[3], aBase + 16u * RPITCH + kk * 32);
        #pragma unroll
        for (int bt = 0; bt < 4; bt++) {             // 4 LDSM -> 8 n8-tiles
            uint32_t b0, b1, b2, b3;
            LDSM4(b0, b1, b2, b3, bBase + (uint32_t)bt * 16 * RPITCH + kk * 32);
            MMA16816(c[0][2*bt],   a0[0], a0[1], a0[2], a0[3], b0, b1);
            MMA16816(c[0][2*bt+1], a0[0], a0[1], a0[2], a0[3], b2, b3);
            MMA16816(c[1][2*bt],   a1[0], a1[1], a1[2], a1[3], b0, b1);
            MMA16816(c[1][2*bt+1], a1[0], a1[1], a1[2], a1[3], b2, b3);
        }
    }

    // ---- epilogue: max over i within each of this warp's 2 b-groups -------
    #pragma unroll
    for (int m = 0; m < 2; m++) {
        const int bl = mq * 2 + m;                   // local b (0..7)
        const int b  = (m0 >> 4) + bl;               // global b
        float rowsum = 0.0f;
        #pragma unroll
        for (int t = 0; t < 8; t++) {
            float m0v = fmaxf(c[m][t][0], c[m][t][2]);
            float m1v = fmaxf(c[m][t][1], c[m][t][3]);
            #pragma unroll
            for (int o = 4; o <= 16; o <<= 1) {
                m0v = fmaxf(m0v, __shfl_xor_sync(0xffffffffu, m0v, o));
                m1v = fmaxf(m1v, __shfl_xor_sync(0xffffffffu, m1v, o));
            }
            if (lane < 4) {
                int colL = nh * 64 + t * 8 + lane * 2;
                int col  = n0 + colL;
                if ((col >> 3) == b) {
                    g_diag[col]     = m0v;
                    g_diag[col + 1] = m1v;
                }
                float e0 = __expf(m0v), e1 = __expf(m1v);
                scol[bl * 128 + colL]     = e0;
                scol[bl * 128 + colL + 1] = e1;
                rowsum += e0 + e1;
            }
        }
        rowsum += __shfl_xor_sync(0xffffffffu, rowsum, 1);
        rowsum += __shfl_xor_sync(0xffffffffu, rowsum, 2);
        if (lane == 0) srow[w][m] = rowsum;
    }

    __syncthreads();
    if (tid < 128) {
        float s = 0.0f;
        #pragma unroll
        for (int bl = 0; bl < 8; bl++) s += scol[bl * 128 + tid];
        g_colpart[(size_t)mb * NCOLS + n0 + tid] = s;
    }
    if (tid < 8) {      // combine the two n-halves of each b's row sum
        int q = tid >> 1, m = tid & 1;
        g_rowpart[nb * BB + (m0 >> 4) + tid] =
            srow[q * 2 + 0][m] + srow[q * 2 + 1][m];
    }

    // ---- last-CTA fused final reduction -----------------------------------
    __threadfence();
    if (tid == 0) slast = atomicInc(&g_cnt, NCTA - 1);
    __syncthreads();
    if (slast != NCTA - 1) return;
    __threadfence();

    for (int col = tid; col < NCOLS; col += 256) {
        float s = 0.0f;
        #pragma unroll 8
        for (int j = 0; j < MBLK; j++) s += g_colpart[(size_t)j * NCOLS + col];
        g_logden[col] = logf(s);
    }
    for (int b = tid; b < BB; b += 256) {
        float s = 0.0f;
        #pragma unroll 8
        for (int j = 0; j < NBLK; j++) s += g_rowpart[j * BB + b];
        g_logrow[b] = logf(s);
    }
    __syncthreads();

    float acc = 0.0f;
    for (int b = tid; b < BB; b += 256) {
        float d = 0.0f, l = 0.0f;
        #pragma unroll
        for (int t = 0; t < TT; t++) {
            d += g_diag[b * TT + t];
            l += g_logden[b * TT + t];
        }
        acc += 1.125f * d - g_logrow[b] - l;    // (1 + 1/T) = 1.125
    }
    sred[tid] = acc; __syncthreads();
    for (int o = 128; o; o >>= 1) {
        if (tid < o) sred[tid] += sred[tid + o];
        __syncthreads();
    }
    if (tid == 0) out[0] = -sred[0];
}

// ---------------------------------------------------------------------------
extern "C" void kernel_launch(void* const* d_in, const int* in_sizes, int n_in,
                              void* d_out, int out_size) {
    const float* img  = (const float*)d_in[0];
    const float* text = (const float*)d_in[1];
    if (n_in >= 2 && in_sizes[0] == NCOLS * DD && in_sizes[1] == MROWS * DD) {
        const float* t = img; img = text; text = t;
    }

    cudaFuncSetAttribute(kgemm, cudaFuncAttributeMaxDynamicSharedMemorySize, SM_BYTES);

    knorm<<<(MROWS + NCOLS) / 8, 256>>>(img, text);
    kgemm<<<dim3(NBLK, MBLK), 256, SM_BYTES>>>((float*)d_out);
}

// round 8
// speedup vs baseline: 1.0065x; 1.0065x over previous
#include <cuda_runtime.h>
#include <cuda_bf16.h>
#include <math.h>
#include <cstdint>

#define BB 512
#define ZI 16
#define TT 8
#define DD 128
#define MROWS (BB*ZI)   /* 8192 */
#define NCOLS (BB*TT)   /* 4096 */

#define NBLK (NCOLS/128)         /* 32 n-blocks */
#define MBLK (MROWS/128)         /* 64 m-blocks */
#define NCTA (NBLK*MBLK)         /* 2048 CTAs   */

// ---------------- scratch (static __device__, allocation-free) -------------
__device__ __nv_bfloat162 g_imgh [(size_t)MROWS * (DD/2)];   // 2 MB
__device__ __nv_bfloat162 g_texth[(size_t)NCOLS * (DD/2)];   // 1 MB
__device__ float g_diag[NCOLS];
__device__ float g_rowpart[NBLK * BB];             // per n-block row sums
__device__ float g_colpart[(size_t)MBLK * NCOLS];  // per m-block col sums
__device__ float g_logden[NCOLS];
__device__ float g_logrow[BB];
__device__ unsigned g_cnt;                         // zero-init, self-resetting

__device__ __forceinline__ uint32_t smem_u32(const void* p) {
    uint32_t a;
    asm("{ .reg .u64 t; cvta.to.shared.u64 t, %1; cvt.u32.u64 %0, t; }"
        : "=r"(a) : "l"(p));
    return a;
}

#define CPASYNC16(dst,src) \
    asm volatile("cp.async.ca.shared.global [%0], [%1], 16;" \
                 :: "r"(dst), "l"(src) : "memory")

#define LDSM4(r0,r1,r2,r3,addr) \
    asm volatile("ldmatrix.sync.aligned.m8n8.x4.shared.b16 {%0,%1,%2,%3}, [%4];" \
                 : "=r"(r0),"=r"(r1),"=r"(r2),"=r"(r3) : "r"(addr))

#define MMA16816(c,a0,a1,a2,a3,b0,b1) \
    asm volatile("mma.sync.aligned.m16n8k16.row.col.f32.bf16.bf16.f32 " \
                 "{%0,%1,%2,%3},{%4,%5,%6,%7},{%8,%9},{%0,%1,%2,%3};" \
                 : "+f"(c[0]),"+f"(c[1]),"+f"(c[2]),"+f"(c[3]) \
                 : "r"(a0),"r"(a1),"r"(a2),"r"(a3),"r"(b0),"r"(b1))

// ---------------------------------------------------------------------------
// 1) L2 normalize + convert to packed bf16. One warp per row of 128 floats.
// ---------------------------------------------------------------------------
__global__ void knorm(const float* __restrict__ img, const float* __restrict__ text) {
    int wid  = blockIdx.x * 8 + (threadIdx.x >> 5);
    int lane = threadIdx.x & 31;
    const float* src; __nv_bfloat162* dst;
    if (wid < MROWS) { src = img + (size_t)wid * DD;  dst = g_imgh + (size_t)wid * (DD/2); }
    else { int r = wid - MROWS; src = text + (size_t)r * DD; dst = g_texth + (size_t)r * (DD/2); }
    float4 v = ((const float4*)src)[lane];
    float s = v.x*v.x + v.y*v.y + v.z*v.z + v.w*v.w;
    #pragma unroll
    for (int o = 16; o; o >>= 1) s += __shfl_xor_sync(0xffffffffu, s, o);
    float inv = 1.0f / fmaxf(sqrtf(s), 1e-12f);
    dst[lane*2]   = __floats2bfloat162_rn(v.x*inv, v.y*inv);
    dst[lane*2+1] = __floats2bfloat162_rn(v.z*inv, v.w*inv);
}

// ---------------------------------------------------------------------------
// 2) HMMA GEMM 128x128x128, 2048 CTAs. Warp tile 32m x 64n (4 mq x 2 nh):
//    per kk-step 6 LDSM.x4 feed 16 MMAs (was 9 per 16) -> -33% smem traffic.
//    Fused max-over-i + exp + partial reductions + last-CTA finale.
// ---------------------------------------------------------------------------
#define RPITCH 272
#define TILE_B (128 * RPITCH)            /* 34816 */
#define SM_BYTES (2 * TILE_B)            /* 69632 dynamic */

__global__ void __launch_bounds__(256) kgemm(float* __restrict__ out) {
    extern __shared__ char sh[];
    char* shA = sh;
    char* shB = sh + TILE_B;
    __shared__ float scol[8 * 128];
    __shared__ float srow[8][2];
    __shared__ float sred[256];
    __shared__ unsigned slast;

    const int tid  = threadIdx.x;
    const int lane = tid & 31, w = tid >> 5;
    const int mq = w >> 1, nh = w & 1;            // warp = (m-quad, n-half)
    const int nb = blockIdx.x, mb = blockIdx.y;
    const int m0 = mb * 128, n0 = nb * 128;

    const uint32_t sAu = smem_u32(shA), sBu = smem_u32(shB);

    // ---- async tile loads: 128 rows x 256B, rows padded to 272B -----------
    const uint4* gA = (const uint4*)(g_imgh  + (size_t)m0 * (DD/2));
    const uint4* gB = (const uint4*)(g_texth + (size_t)n0 * (DD/2));
    #pragma unroll
    for (int it = tid; it < 2048; it += 256) {
        int row = it >> 4, q = it & 15;
        uint32_t so = row * RPITCH + q * 16;
        CPASYNC16(sAu + so, gA + it);
        CPASYNC16(sBu + so, gB + it);
    }
    asm volatile("cp.async.commit_group;" ::: "memory");
    asm volatile("cp.async.wait_group 0;" ::: "memory");
    __syncthreads();

    // A: two m16 tiles at rows mq*32 and mq*32+16
    const uint32_t aBase = sAu + (uint32_t)(mq * 32 + (lane & 15)) * RPITCH
                               + (uint32_t)(lane >> 4) * 16;
    // B: lanes 0-7 rows n..n+8 klo | 8-15 khi | 16-23 n+8..16 klo | 24-31 khi
    const uint32_t bBase = sBu + (uint32_t)(nh * 64 + (lane & 7) + ((lane >> 4) << 3)) * RPITCH
                               + (uint32_t)((lane >> 3) & 1) * 16;

    float c[2][8][4];
    #pragma unroll
    for (int m = 0; m < 2; m++)
        #pragma unroll
        for (int t = 0; t < 8; t++)
            #pragma unroll
            for (int j = 0; j < 4; j++) c[m][t][j] = 0.0f;

    #pragma unroll
    for (int kk = 0; kk < 8; kk++) {                 // K = 8 * 16
        uint32_t a0[4], a1[4];
        LDSM4(a0[0], a0[1], a0[2], a0[3], aBase + kk * 32);
        LDSM4(a1[0], a1[1], a1[2], a1[3], aBase + 16u * RPITCH + kk * 32);
        #pragma unroll
        for (int bt = 0; bt < 4; bt++) {             // 4 LDSM -> 8 n8-tiles
            uint32_t b0, b1, b2, b3;
            LDSM4(b0, b1, b2, b3, bBase + (uint32_t)bt * 16 * RPITCH + kk * 32);
            MMA16816(c[0][2*bt],   a0[0], a0[1], a0[2], a0[3], b0, b1);
            MMA16816(c[0][2*bt+1], a0[0], a0[1], a0[2], a0[3], b2, b3);
            MMA16816(c[1][2*bt],   a1[0], a1[1], a1[2], a1[3], b0, b1);
            MMA16816(c[1][2*bt+1], a1[0], a1[1], a1[2], a1[3], b2, b3);
        }
    }

    // ---- epilogue: max over i within each of this warp's 2 b-groups -------
    #pragma unroll
    for (int m = 0; m < 2; m++) {
        const int bl = mq * 2 + m;                   // local b (0..7)
        const int b  = (m0 >> 4) + bl;               // global b
        float rowsum = 0.0f;
        #pragma unroll
        for (int t = 0; t < 8; t++) {
            float m0v = fmaxf(c[m][t][0], c[m][t][2]);
            float m1v = fmaxf(c[m][t][1], c[m][t][3]);
            #pragma unroll
            for (int o = 4; o <= 16; o <<= 1) {
                m0v = fmaxf(m0v, __shfl_xor_sync(0xffffffffu, m0v, o));
                m1v = fmaxf(m1v, __shfl_xor_sync(0xffffffffu, m1v, o));
            }
            if (lane < 4) {
                int colL = nh * 64 + t * 8 + lane * 2;
                int col  = n0 + colL;
                if ((col >> 3) == b) {
                    g_diag[col]     = m0v;
                    g_diag[col + 1] = m1v;
                }
                float e0 = __expf(m0v), e1 = __expf(m1v);
                scol[bl * 128 + colL]     = e0;
                scol[bl * 128 + colL + 1] = e1;
                rowsum += e0 + e1;
            }
        }
        rowsum += __shfl_xor_sync(0xffffffffu, rowsum, 1);
        rowsum += __shfl_xor_sync(0xffffffffu, rowsum, 2);
        if (lane == 0) srow[w][m] = rowsum;
    }

    __syncthreads();
    if (tid < 128) {
        float s = 0.0f;
        #pragma unroll
        for (int bl = 0; bl < 8; bl++) s += scol[bl * 128 + tid];
        g_colpart[(size_t)mb * NCOLS + n0 + tid] = s;
    }
    if (tid < 8) {      // combine the two n-halves of each b's row sum
        int q = tid >> 1, m = tid & 1;
        g_rowpart[nb * BB + (m0 >> 4) + tid] =
            srow[q * 2 + 0][m] + srow[q * 2 + 1][m];
    }

    // ---- last-CTA fused final reduction -----------------------------------
    __threadfence();
    if (tid == 0) slast = atomicInc(&g_cnt, NCTA - 1);
    __syncthreads();
    if (slast != NCTA - 1) return;
    __threadfence();

    for (int col = tid; col < NCOLS; col += 256) {
        float s = 0.0f;
        #pragma unroll 8
        for (int j = 0; j < MBLK; j++) s += g_colpart[(size_t)j * NCOLS + col];
        g_logden[col] = logf(s);
    }
    for (int b = tid; b < BB; b += 256) {
        float s = 0.0f;
        #pragma unroll 8
        for (int j = 0; j < NBLK; j++) s += g_rowpart[j * BB + b];
        g_logrow[b] = logf(s);
    }
    __syncthreads();

    float acc = 0.0f;
    for (int b = tid; b < BB; b += 256) {
        float d = 0.0f, l = 0.0f;
        #pragma unroll
        for (int t = 0; t < TT; t++) {
            d += g_diag[b * TT + t];
            l += g_logden[b * TT + t];
        }
        acc += 1.125f * d - g_logrow[b] - l;    // (1 + 1/T) = 1.125
    }
    sred[tid] = acc; __syncthreads();
    for (int o = 128; o; o >>= 1) {
        if (tid < o) sred[tid] += sred[tid + o];
        __syncthreads();
    }
    if (tid == 0) out[0] = -sred[0];
}

// ---------------------------------------------------------------------------
extern "C" void kernel_launch(void* const* d_in, const int* in_sizes, int n_in,
                              void* d_out, int out_size) {
    const float* img  = (const float*)d_in[0];
    const float* text = (const float*)d_in[1];
    if (n_in >= 2 && in_sizes[0] == NCOLS * DD && in_sizes[1] == MROWS * DD) {
        const float* t = img; img = text; text = t;
    }

    cudaFuncSetAttribute(kgemm, cudaFuncAttributeMaxDynamicSharedMemorySize, SM_BYTES);

    knorm<<<(MROWS + NCOLS) / 8, 256>>>(img, text);
    kgemm<<<dim3(NBLK, MBLK), 256, SM_BYTES>>>((float*)d_out);
}

// round 9
// speedup vs baseline: 1.0095x; 1.0030x over previous
#include <cuda_runtime.h>
#include <cuda_bf16.h>
#include <math.h>
#include <cstdint>

#define BB 512
#define ZI 16
#define TT 8
#define DD 128
#define MROWS (BB*ZI)   /* 8192 */
#define NCOLS (BB*TT)   /* 4096 */

#define NBLK (NCOLS/128)         /* 32 n-blocks */
#define MBLK (MROWS/128)         /* 64 m-blocks */
#define NCTA (NBLK*MBLK)         /* 2048 CTAs   */

// ---------------- scratch (static __device__, allocation-free) -------------
__device__ __nv_bfloat162 g_imgh [(size_t)MROWS * (DD/2)];   // 2 MB
__device__ __nv_bfloat162 g_texth[(size_t)NCOLS * (DD/2)];   // 1 MB
__device__ float g_diag[NCOLS];
__device__ float g_rowpart[NBLK * BB];             // per n-block row sums
__device__ float g_colpart[(size_t)MBLK * NCOLS];  // per m-block col sums
__device__ float g_logden[NCOLS];
__device__ float g_logrow[BB];
__device__ unsigned g_cnt;                         // zero-init, self-resetting

__device__ __forceinline__ uint32_t smem_u32(const void* p) {
    uint32_t a;
    asm("{ .reg .u64 t; cvta.to.shared.u64 t, %1; cvt.u32.u64 %0, t; }"
        : "=r"(a) : "l"(p));
    return a;
}

#define CPASYNC16(dst,src) \
    asm volatile("cp.async.ca.shared.global [%0], [%1], 16;" \
                 :: "r"(dst), "l"(src) : "memory")

#define LDSM4(r0,r1,r2,r3,addr) \
    asm volatile("ldmatrix.sync.aligned.m8n8.x4.shared.b16 {%0,%1,%2,%3}, [%4];" \
                 : "=r"(r0),"=r"(r1),"=r"(r2),"=r"(r3) : "r"(addr))

#define MMA16816(c,a0,a1,a2,a3,b0,b1) \
    asm volatile("mma.sync.aligned.m16n8k16.row.col.f32.bf16.bf16.f32 " \
                 "{%0,%1,%2,%3},{%4,%5,%6,%7},{%8,%9},{%0,%1,%2,%3};" \
                 : "+f"(c[0]),"+f"(c[1]),"+f"(c[2]),"+f"(c[3]) \
                 : "r"(a0),"r"(a1),"r"(a2),"r"(a3),"r"(b0),"r"(b1))

// ---------------------------------------------------------------------------
// 1) L2 normalize + convert to packed bf16. One warp per row of 128 floats.
// ---------------------------------------------------------------------------
__global__ void knorm(const float* __restrict__ img, const float* __restrict__ text) {
    int wid  = blockIdx.x * 8 + (threadIdx.x >> 5);
    int lane = threadIdx.x & 31;
    const float* src; __nv_bfloat162* dst;
    if (wid < MROWS) { src = img + (size_t)wid * DD;  dst = g_imgh + (size_t)wid * (DD/2); }
    else { int r = wid - MROWS; src = text + (size_t)r * DD; dst = g_texth + (size_t)r * (DD/2); }
    float4 v = ((const float4*)src)[lane];
    float s = v.x*v.x + v.y*v.y + v.z*v.z + v.w*v.w;
    #pragma unroll
    for (int o = 16; o; o >>= 1) s += __shfl_xor_sync(0xffffffffu, s, o);
    float inv = 1.0f / fmaxf(sqrtf(s), 1e-12f);
    dst[lane*2]   = __floats2bfloat162_rn(v.x*inv, v.y*inv);
    dst[lane*2+1] = __floats2bfloat162_rn(v.z*inv, v.w*inv);
}

// ---------------------------------------------------------------------------
// 2) HMMA GEMM 128x128x128, 2048 CTAs. Warp tile 32m x 64n (4 mq x 2 nh):
//    per kk-step 6 LDSM.x4 feed 16 MMAs (was 9 per 16) -> -33% smem traffic.
//    Fused max-over-i + exp + partial reductions + last-CTA finale.
// ---------------------------------------------------------------------------
#define RPITCH 272
#define TILE_B (128 * RPITCH)            /* 34816 */
#define SM_BYTES (2 * TILE_B)            /* 69632 dynamic */

__global__ void __launch_bounds__(256) kgemm(float* __restrict__ out) {
    extern __shared__ char sh[];
    char* shA = sh;
    char* shB = sh + TILE_B;
    __shared__ float scol[8 * 128];
    __shared__ float srow[8][2];
    __shared__ float sred[256];
    __shared__ unsigned slast;

    const int tid  = threadIdx.x;
    const int lane = tid & 31, w = tid >> 5;
    const int mq = w >> 1, nh = w & 1;            // warp = (m-quad, n-half)
    const int nb = blockIdx.x, mb = blockIdx.y;
    const int m0 = mb * 128, n0 = nb * 128;

    const uint32_t sAu = smem_u32(shA), sBu = smem_u32(shB);

    // ---- async tile loads: 128 rows x 256B, rows padded to 272B -----------
    const uint4* gA = (const uint4*)(g_imgh  + (size_t)m0 * (DD/2));
    const uint4* gB = (const uint4*)(g_texth + (size_t)n0 * (DD/2));
    #pragma unroll
    for (int it = tid; it < 2048; it += 256) {
        int row = it >> 4, q = it & 15;
        uint32_t so = row * RPITCH + q * 16;
        CPASYNC16(sAu + so, gA + it);
        CPASYNC16(sBu + so, gB + it);
    }
    asm volatile("cp.async.commit_group;" ::: "memory");
    asm volatile("cp.async.wait_group 0;" ::: "memory");
    __syncthreads();

    // A: two m16 tiles at rows mq*32 and mq*32+16
    const uint32_t aBase = sAu + (uint32_t)(mq * 32 + (lane & 15)) * RPITCH
                               + (uint32_t)(lane >> 4) * 16;
    // B: lanes 0-7 rows n..n+8 klo | 8-15 khi | 16-23 n+8..16 klo | 24-31 khi
    const uint32_t bBase = sBu + (uint32_t)(nh * 64 + (lane & 7) + ((lane >> 4) << 3)) * RPITCH
                               + (uint32_t)((lane >> 3) & 1) * 16;

    float c[2][8][4];
    #pragma unroll
    for (int m = 0; m < 2; m++)
        #pragma unroll
        for (int t = 0; t < 8; t++)
            #pragma unroll
            for (int j = 0; j < 4; j++) c[m][t][j] = 0.0f;

    #pragma unroll
    for (int kk = 0; kk < 8; kk++) {                 // K = 8 * 16
        uint32_t a0[4], a1[4];
        LDSM4(a0[0], a0[1], a0[2], a0[3], aBase + kk * 32);
        LDSM4(a1[0], a1[1], a1[2], a1[3], aBase + 16u * RPITCH + kk * 32);
        #pragma unroll
        for (int bt = 0; bt < 4; bt++) {             // 4 LDSM -> 8 n8-tiles
            uint32_t b0, b1, b2, b3;
            LDSM4(b0, b1, b2, b3, bBase + (uint32_t)bt * 16 * RPITCH + kk * 32);
            MMA16816(c[0][2*bt],   a0[0], a0[1], a0[2], a0[3], b0, b1);
            MMA16816(c[0][2*bt+1], a0[0], a0[1], a0[2], a0[3], b2, b3);
            MMA16816(c[1][2*bt],   a1[0], a1[1], a1[2], a1[3], b0, b1);
            MMA16816(c[1][2*bt+1], a1[0], a1[1], a1[2], a1[3], b2, b3);
        }
    }

    // ---- epilogue: max over i within each of this warp's 2 b-groups -------
    #pragma unroll
    for (int m = 0; m < 2; m++) {
        const int bl = mq * 2 + m;                   // local b (0..7)
        const int b  = (m0 >> 4) + bl;               // global b
        float rowsum = 0.0f;
        #pragma unroll
        for (int t = 0; t < 8; t++) {
            float m0v = fmaxf(c[m][t][0], c[m][t][2]);
            float m1v = fmaxf(c[m][t][1], c[m][t][3]);
            #pragma unroll
            for (int o = 4; o <= 16; o <<= 1) {
                m0v = fmaxf(m0v, __shfl_xor_sync(0xffffffffu, m0v, o));
                m1v = fmaxf(m1v, __shfl_xor_sync(0xffffffffu, m1v, o));
            }
            if (lane < 4) {
                int colL = nh * 64 + t * 8 + lane * 2;
                int col  = n0 + colL;
                if ((col >> 3) == b) {
                    g_diag[col]     = m0v;
                    g_diag[col + 1] = m1v;
                }
                float e0 = __expf(m0v), e1 = __expf(m1v);
                scol[bl * 128 + colL]     = e0;
                scol[bl * 128 + colL + 1] = e1;
                rowsum += e0 + e1;
            }
        }
        rowsum += __shfl_xor_sync(0xffffffffu, rowsum, 1);
        rowsum += __shfl_xor_sync(0xffffffffu, rowsum, 2);
        if (lane == 0) srow[w][m] = rowsum;
    }

    __syncthreads();
    if (tid < 128) {
        float s = 0.0f;
        #pragma unroll
        for (int bl = 0; bl < 8; bl++) s += scol[bl * 128 + tid];
        g_colpart[(size_t)mb * NCOLS + n0 + tid] = s;
    }
    if (tid < 8) {      // combine the two n-halves of each b's row sum
        int q = tid >> 1, m = tid & 1;
        g_rowpart[nb * BB + (m0 >> 4) + tid] =
            srow[q * 2 + 0][m] + srow[q * 2 + 1][m];
    }

    // ---- last-CTA fused final reduction -----------------------------------
    __threadfence();
    if (tid == 0) slast = atomicInc(&g_cnt, NCTA - 1);
    __syncthreads();
    if (slast != NCTA - 1) return;
    __threadfence();

    for (int col = tid; col < NCOLS; col += 256) {
        float s = 0.0f;
        #pragma unroll 8
        for (int j = 0; j < MBLK; j++) s += g_colpart[(size_t)j * NCOLS + col];
        g_logden[col] = logf(s);
    }
    for (int b = tid; b < BB; b += 256) {
        float s = 0.0f;
        #pragma unroll 8
        for (int j = 0; j < NBLK; j++) s += g_rowpart[j * BB + b];
        g_logrow[b] = logf(s);
    }
    __syncthreads();

    float acc = 0.0f;
    for (int b = tid; b < BB; b += 256) {
        float d = 0.0f, l = 0.0f;
        #pragma unroll
        for (int t = 0; t < TT; t++) {
            d += g_diag[b * TT + t];
            l += g_logden[b * TT + t];
        }
        acc += 1.125f * d - g_logrow[b] - l;    // (1 + 1/T) = 1.125
    }
    sred[tid] = acc; __syncthreads();
    for (int o = 128; o; o >>= 1) {
        if (tid < o) sred[tid] += sred[tid + o];
        __syncthreads();
    }
    if (tid == 0) out[0] = -sred[0];
}

// ---------------------------------------------------------------------------
extern "C" void kernel_launch(void* const* d_in, const int* in_sizes, int n_in,
                              void* d_out, int out_size) {
    const float* img  = (const float*)d_in[0];
    const float* text = (const float*)d_in[1];
    if (n_in >= 2 && in_sizes[0] == NCOLS * DD && in_sizes[1] == MROWS * DD) {
        const float* t = img; img = text; text = t;
    }

    cudaFuncSetAttribute(kgemm, cudaFuncAttributeMaxDynamicSharedMemorySize, SM_BYTES);

    knorm<<<(MROWS + NCOLS) / 8, 256>>>(img, text);
    kgemm<<<dim3(NBLK, MBLK), 256, SM_BYTES>>>((float*)d_out);
}